// round 2
// baseline (speedup 1.0000x reference)
#include <cuda_runtime.h>
#include <cuda_bf16.h>
#include <cstdint>

// ---------------- Problem constants ----------------
#define NN    10000     // nodes
#define SEQ   96
#define HID   128
#define HEADS 8
#define HC    (HID*HEADS)   // 1024
#define OUTC  768
#define EMAX  160000
#define NEG_SLOPE 0.2f

// ---------------- Scratch (device globals; no allocation allowed) ------------
__device__ float g_bufA[NN * HC];      // 40 MB : GEMM output h of current layer
__device__ float g_bufB[NN * HC];      // 40 MB : layer input / aggregation ping-pong
__device__ float g_xT[NN * SEQ];       // transposed input
__device__ float g_asrc[NN * HEADS];
__device__ float g_adst[NN * HEADS];
__device__ float g_alpha[EMAX * HEADS];  // E*H raw alpha -> exp values
__device__ int   g_amax[NN * HEADS];
__device__ float g_denom[NN * HEADS];
__device__ float g_ce[HEADS];

// ---------------- Transpose x: [S,N] -> [N,S] ----------------
__global__ void transpose_x_kernel(const float* __restrict__ x, float* __restrict__ xT,
                                   int n, int s) {
    int i = blockIdx.x * blockDim.x + threadIdx.x;   // i = sr*n + nc of source
    if (i >= n * s) return;
    int sr = i / n, nc = i % n;
    xT[(size_t)nc * s + sr] = x[i];
}

// ---------------- Tiled SGEMM: C[M,N] = A[M,K] * B[K,N] (row-major) ----------
// BM=BN=128, BK=8, TM=TN=8, 256 threads. K must be a multiple of 8 (96/1024 ok).
__global__ __launch_bounds__(256) void sgemm_kernel(
    const float* __restrict__ A, const float* __restrict__ B, float* __restrict__ C,
    int M, int N, int K) {
    const int BM = 128, BN = 128, BK = 8, TM = 8, TN = 8;
    __shared__ float As[BK][BM];
    __shared__ float Bs[BK][BN];
    const int tid = threadIdx.x;
    const int bM = blockIdx.y * BM;
    const int bN = blockIdx.x * BN;
    const int trow = (tid / 16) * TM;
    const int tcol = (tid % 16) * TN;
    const int aRow = tid >> 1, aCol = (tid & 1) * 4;     // 128 rows x 8 cols
    const int bRow = tid >> 5, bCol = (tid & 31) * 4;    // 8 rows x 128 cols

    float acc[TM][TN];
    #pragma unroll
    for (int i = 0; i < TM; i++)
        #pragma unroll
        for (int j = 0; j < TN; j++) acc[i][j] = 0.f;

    for (int k0 = 0; k0 < K; k0 += BK) {
        float4 av = make_float4(0.f, 0.f, 0.f, 0.f);
        int arow_g = bM + aRow;
        if (arow_g < M)
            av = *reinterpret_cast<const float4*>(A + (size_t)arow_g * K + k0 + aCol);
        As[aCol + 0][aRow] = av.x;
        As[aCol + 1][aRow] = av.y;
        As[aCol + 2][aRow] = av.z;
        As[aCol + 3][aRow] = av.w;
        float4 bv = make_float4(0.f, 0.f, 0.f, 0.f);
        int bcol_g = bN + bCol;
        if (bcol_g < N)
            bv = *reinterpret_cast<const float4*>(B + (size_t)(k0 + bRow) * N + bcol_g);
        *reinterpret_cast<float4*>(&Bs[bRow][bCol]) = bv;
        __syncthreads();

        #pragma unroll
        for (int kk = 0; kk < BK; kk++) {
            float a[TM], b[TN];
            #pragma unroll
            for (int i = 0; i < TM; i++) a[i] = As[kk][trow + i];
            #pragma unroll
            for (int j = 0; j < TN; j++) b[j] = Bs[kk][tcol + j];
            #pragma unroll
            for (int i = 0; i < TM; i++)
                #pragma unroll
                for (int j = 0; j < TN; j++)
                    acc[i][j] = fmaf(a[i], b[j], acc[i][j]);
        }
        __syncthreads();
    }

    #pragma unroll
    for (int i = 0; i < TM; i++) {
        int row = bM + trow + i;
        if (row >= M) continue;
        #pragma unroll
        for (int j = 0; j < TN; j += 4) {
            int col = bN + tcol + j;
            if (col < N) {
                float4 v = make_float4(acc[i][j], acc[i][j+1], acc[i][j+2], acc[i][j+3]);
                *reinterpret_cast<float4*>(C + (size_t)row * N + col) = v;
            }
        }
    }
}

// ---------------- Per-(node,head) attention dot products ----------------
// grid = (N, H), block = 128
__global__ void attn_coef_kernel(const float* __restrict__ h,
                                 const float* __restrict__ ws_all,
                                 const float* __restrict__ wd_all,
                                 float* __restrict__ asrc, float* __restrict__ adst,
                                 int H, int C) {
    int n = blockIdx.x, hd = blockIdx.y;
    const float* row = h + ((size_t)n * H + hd) * C;
    const float* ws = ws_all + (size_t)hd * C;
    const float* wd = wd_all + (size_t)hd * C;
    float ss = 0.f, sd = 0.f;
    for (int c = threadIdx.x; c < C; c += blockDim.x) {
        float v = row[c];
        ss += v * ws[c];
        sd += v * wd[c];
    }
    #pragma unroll
    for (int o = 16; o; o >>= 1) {
        ss += __shfl_down_sync(0xffffffffu, ss, o);
        sd += __shfl_down_sync(0xffffffffu, sd, o);
    }
    __shared__ float sss[8], ssd[8];
    int w = threadIdx.x >> 5, l = threadIdx.x & 31;
    if (l == 0) { sss[w] = ss; ssd[w] = sd; }
    __syncthreads();
    if (threadIdx.x == 0) {
        float a = 0.f, b = 0.f;
        int nw = blockDim.x >> 5;
        for (int i = 0; i < nw; i++) { a += sss[i]; b += ssd[i]; }
        asrc[n * H + hd] = a;
        adst[n * H + hd] = b;
    }
}

// ---------------- ce[h] = dot(We[h,:], ae[h,:]) ; grid = H, block = 128 ------
__global__ void ce_kernel(const float* __restrict__ We, const float* __restrict__ ae,
                          float* __restrict__ ce, int C) {
    int hd = blockIdx.x;
    float s = 0.f;
    for (int c = threadIdx.x; c < C; c += blockDim.x)
        s += We[(size_t)hd * C + c] * ae[(size_t)hd * C + c];
    #pragma unroll
    for (int o = 16; o; o >>= 1) s += __shfl_down_sync(0xffffffffu, s, o);
    __shared__ float sm[8];
    int w = threadIdx.x >> 5, l = threadIdx.x & 31;
    if (l == 0) sm[w] = s;
    __syncthreads();
    if (threadIdx.x == 0) {
        float a = 0.f;
        int nw = blockDim.x >> 5;
        for (int i = 0; i < nw; i++) a += sm[i];
        ce[hd] = a;
    }
}

// ---------------- init amax/denom ----------------
__global__ void init_softmax_kernel(int* __restrict__ amax, float* __restrict__ denom, int total) {
    int i = blockIdx.x * blockDim.x + threadIdx.x;
    if (i >= total) return;
    amax[i] = INT_MIN;
    denom[i] = 0.f;
}

__device__ __forceinline__ int float_enc(float f) {
    int i = __float_as_int(f);
    return i >= 0 ? i : (i ^ 0x7fffffff);
}
__device__ __forceinline__ float float_dec(int i) {
    return __int_as_float(i >= 0 ? i : (i ^ 0x7fffffff));
}

// ---------------- edge pass 1: raw alpha + segment max (thread per edge) -----
__global__ void edge_alpha_kernel(const int* __restrict__ src, const int* __restrict__ dst,
                                  const float* __restrict__ ew,
                                  const float* __restrict__ asrc, const float* __restrict__ adst,
                                  const float* __restrict__ ce,
                                  float* __restrict__ alpha, int* __restrict__ amax,
                                  int E, int H) {
    int e = blockIdx.x * blockDim.x + threadIdx.x;
    if (e >= E) return;
    int s = src[e], d = dst[e];
    float w = ew[e];
    #pragma unroll
    for (int h = 0; h < HEADS; h++) {
        if (h >= H) break;
        float a = asrc[s * H + h] + adst[d * H + h] + w * ce[h];
        a = a > 0.f ? a : NEG_SLOPE * a;
        alpha[(size_t)e * H + h] = a;
        atomicMax(&amax[d * H + h], float_enc(a));
    }
}

// ---------------- edge pass 2: exp + segment sum (thread per edge) -----------
__global__ void edge_exp_kernel(const int* __restrict__ dst,
                                float* __restrict__ alpha,
                                const int* __restrict__ amax, float* __restrict__ denom,
                                int E, int H) {
    int e = blockIdx.x * blockDim.x + threadIdx.x;
    if (e >= E) return;
    int d = dst[e];
    #pragma unroll
    for (int h = 0; h < HEADS; h++) {
        if (h >= H) break;
        float m = float_dec(amax[d * H + h]);
        float ex = __expf(alpha[(size_t)e * H + h] - m);
        alpha[(size_t)e * H + h] = ex;
        atomicAdd(&denom[d * H + h], ex);
    }
}

// ---------------- edge pass 3: scatter messages (warp per edge-head) ---------
__global__ void edge_scatter_kernel(const int* __restrict__ src, const int* __restrict__ dst,
                                    const float* __restrict__ h,
                                    const float* __restrict__ exv, const float* __restrict__ denom,
                                    float* __restrict__ out, int E, int H, int C) {
    int gw = (blockIdx.x * blockDim.x + threadIdx.x) >> 5;
    int lane = threadIdx.x & 31;
    if (gw >= E * H) return;
    int e = gw / H, hd = gw % H;
    int s = src[e], d = dst[e];
    float al = exv[(size_t)e * H + hd] / (denom[d * H + hd] + 1e-16f);
    const float* hp = h + ((size_t)s * H + hd) * C;
    float* op = out + ((size_t)d * H + hd) * C;
    for (int c = lane * 4; c < C; c += 128) {
        float4 v = *reinterpret_cast<const float4*>(hp + c);
        atomicAdd(op + c + 0, v.x * al);
        atomicAdd(op + c + 1, v.y * al);
        atomicAdd(op + c + 2, v.z * al);
        atomicAdd(op + c + 3, v.w * al);
    }
}

// ---------------- in-place bias (+ optional relu) ----------------
__global__ void bias_act_kernel(float* __restrict__ y, const float* __restrict__ bias,
                                int total, int F, int do_relu) {
    int i = blockIdx.x * blockDim.x + threadIdx.x;
    if (i >= total) return;
    float v = y[i] + bias[i % F];
    if (do_relu) v = fmaxf(v, 0.f);
    y[i] = v;
}

// ---------------- host-side layer driver ----------------
static void run_gat_layer(const float* in, int F_in,
                          const float* W, const float* a_s, const float* a_d,
                          const float* We, const float* ae, const float* bias,
                          int H, int C,
                          float* hbuf, float* out_agg,
                          float* asrc, float* adst, float* alpha,
                          int* amax, float* denom, float* ce,
                          const int* src, const int* dst, const float* ew, int E,
                          int do_relu) {
    int F_out = H * C;
    // 1. h = in @ W
    dim3 ggrid((F_out + 127) / 128, (NN + 127) / 128);
    sgemm_kernel<<<ggrid, 256>>>(in, W, hbuf, NN, F_out, F_in);
    // 2. attention dots
    attn_coef_kernel<<<dim3(NN, H), 128>>>(hbuf, a_s, a_d, asrc, adst, H, C);
    // 3. ce scalars
    ce_kernel<<<H, 128>>>(We, ae, ce, C);
    // 4. softmax state init + agg zero
    int nh = NN * H;
    init_softmax_kernel<<<(nh + 255) / 256, 256>>>(amax, denom, nh);
    cudaMemsetAsync(out_agg, 0, (size_t)NN * F_out * sizeof(float), 0);
    // 5-7. edge passes
    edge_alpha_kernel<<<(E + 255) / 256, 256>>>(src, dst, ew, asrc, adst, ce, alpha, amax, E, H);
    edge_exp_kernel<<<(E + 255) / 256, 256>>>(dst, alpha, amax, denom, E, H);
    long long thr = (long long)E * H * 32;
    edge_scatter_kernel<<<(int)((thr + 255) / 256), 256>>>(src, dst, hbuf, alpha, denom, out_agg, E, H, C);
    // 8. bias (+relu)
    int tot = NN * F_out;
    bias_act_kernel<<<(tot + 255) / 256, 256>>>(out_agg, bias, tot, F_out, do_relu);
}

extern "C" void kernel_launch(void* const* d_in, const int* in_sizes, int n_in,
                              void* d_out, int out_size) {
    const float* x   = (const float*)d_in[0];
    const int*   ei  = (const int*)d_in[1];
    const float* ew  = (const float*)d_in[2];
    const float* W1  = (const float*)d_in[3];
    const float* as1 = (const float*)d_in[4];
    const float* ad1 = (const float*)d_in[5];
    const float* We1 = (const float*)d_in[6];
    const float* ae1 = (const float*)d_in[7];
    const float* b1  = (const float*)d_in[8];
    const float* W2  = (const float*)d_in[9];
    const float* as2 = (const float*)d_in[10];
    const float* ad2 = (const float*)d_in[11];
    const float* We2 = (const float*)d_in[12];
    const float* ae2 = (const float*)d_in[13];
    const float* b2  = (const float*)d_in[14];
    const float* W3  = (const float*)d_in[15];
    const float* as3 = (const float*)d_in[16];
    const float* ad3 = (const float*)d_in[17];
    const float* We3 = (const float*)d_in[18];
    const float* ae3 = (const float*)d_in[19];
    const float* b3  = (const float*)d_in[20];

    const int E = in_sizes[2];
    const int* src = ei;
    const int* dst = ei + E;

    float *bufA, *bufB, *xT, *asrc, *adst, *alpha, *denom, *ce;
    int* amax;
    cudaGetSymbolAddress((void**)&bufA,  g_bufA);
    cudaGetSymbolAddress((void**)&bufB,  g_bufB);
    cudaGetSymbolAddress((void**)&xT,    g_xT);
    cudaGetSymbolAddress((void**)&asrc,  g_asrc);
    cudaGetSymbolAddress((void**)&adst,  g_adst);
    cudaGetSymbolAddress((void**)&alpha, g_alpha);
    cudaGetSymbolAddress((void**)&amax,  g_amax);
    cudaGetSymbolAddress((void**)&denom, g_denom);
    cudaGetSymbolAddress((void**)&ce,    g_ce);

    float* out = (float*)d_out;

    // Transpose x: [1, SEQ, N] -> [N, SEQ]
    int ts = NN * SEQ;
    transpose_x_kernel<<<(ts + 255) / 256, 256>>>(x, xT, NN, SEQ);

    // Layer 1: in = xT [N,96], H=8, C=128, relu. h -> bufA, agg -> bufB
    run_gat_layer(xT, SEQ, W1, as1, ad1, We1, ae1, b1, HEADS, HID,
                  bufA, bufB, asrc, adst, alpha, amax, denom, ce,
                  src, dst, ew, E, 1);

    // Layer 2: in = bufB [N,1024]. h -> bufA, agg -> bufB (input consumed by GEMM first)
    run_gat_layer(bufB, HC, W2, as2, ad2, We2, ae2, b2, HEADS, HID,
                  bufA, bufB, asrc, adst, alpha, amax, denom, ce,
                  src, dst, ew, E, 1);

    // Layer 3: in = bufB, H=1, C=768, no relu, agg -> d_out
    run_gat_layer(bufB, HC, W3, as3, ad3, We3, ae3, b3, 1, OUTC,
                  bufA, out, asrc, adst, alpha, amax, denom, ce,
                  src, dst, ew, E, 0);
}

// round 3
// speedup vs baseline: 1.6993x; 1.6993x over previous
#include <cuda_runtime.h>
#include <cuda_bf16.h>
#include <cstdint>

// ---------------- Problem constants ----------------
#define NN    10000
#define SEQ   96
#define HID   128
#define HEADS 8
#define HC    (HID*HEADS)   // 1024
#define OUTC  768
#define EMAX  160000
#define NEG_SLOPE 0.2f

// ---------------- Scratch (device globals) ----------------
__device__ float g_bufA[NN * HC];
__device__ float g_bufB[NN * HC];
__device__ float g_xT[NN * SEQ];
__device__ float g_asrc[NN * HEADS];
__device__ float g_adst[NN * HEADS];
__device__ float g_alpha[EMAX * HEADS];   // CSR-ordered exp(alpha) values
__device__ float g_denom[NN * HEADS];
__device__ float g_ce[HEADS];
// CSR
__device__ int   g_deg[NN];
__device__ int   g_rowptr[NN + 1];
__device__ int   g_cursor[NN];
__device__ int   g_esrc[EMAX];            // src node per CSR slot
__device__ float g_eew[EMAX];             // edge weight per CSR slot

// ---------------- Transpose x: [S,N] -> [N,S] ----------------
__global__ void transpose_x_kernel(const float* __restrict__ x, float* __restrict__ xT,
                                   int n, int s) {
    int i = blockIdx.x * blockDim.x + threadIdx.x;
    if (i >= n * s) return;
    int sr = i / n, nc = i % n;
    xT[(size_t)nc * s + sr] = x[i];
}

// ---------------- CSR build ----------------
__global__ void zero_deg_kernel(int* __restrict__ deg, int n) {
    int i = blockIdx.x * blockDim.x + threadIdx.x;
    if (i < n) deg[i] = 0;
}
__global__ void hist_kernel(const int* __restrict__ dst, int* __restrict__ deg, int E) {
    int e = blockIdx.x * blockDim.x + threadIdx.x;
    if (e < E) atomicAdd(&deg[dst[e]], 1);
}
// single-block exclusive scan over n elements -> rowptr[0..n]
__global__ __launch_bounds__(1024) void scan_kernel(const int* __restrict__ deg,
                                                    int* __restrict__ rowptr, int n) {
    __shared__ int warp_sums[32];
    const int T = 1024;
    int tid = threadIdx.x;
    int chunk = (n + T - 1) / T;
    int start = tid * chunk;
    int local = 0;
    for (int i = 0; i < chunk; i++) {
        int idx = start + i;
        if (idx < n) local += deg[idx];
    }
    int lane = tid & 31, w = tid >> 5;
    int v = local;
    #pragma unroll
    for (int o = 1; o < 32; o <<= 1) {
        int t = __shfl_up_sync(0xffffffffu, v, o);
        if (lane >= o) v += t;
    }
    if (lane == 31) warp_sums[w] = v;
    __syncthreads();
    if (w == 0) {
        int s = warp_sums[lane];
        #pragma unroll
        for (int o = 1; o < 32; o <<= 1) {
            int t = __shfl_up_sync(0xffffffffu, s, o);
            if (lane >= o) s += t;
        }
        warp_sums[lane] = s;
    }
    __syncthreads();
    int excl = v - local + (w > 0 ? warp_sums[w - 1] : 0);
    int run = excl;
    for (int i = 0; i < chunk; i++) {
        int idx = start + i;
        if (idx < n) { rowptr[idx] = run; run += deg[idx]; }
    }
    if (start < n && start + chunk >= n) rowptr[n] = run;   // thread covering last element
}
__global__ void copy_cursor_kernel(const int* __restrict__ rowptr, int* __restrict__ cursor, int n) {
    int i = blockIdx.x * blockDim.x + threadIdx.x;
    if (i < n) cursor[i] = rowptr[i];
}
__global__ void build_csr_kernel(const int* __restrict__ src, const int* __restrict__ dst,
                                 const float* __restrict__ ew,
                                 int* __restrict__ cursor,
                                 int* __restrict__ esrc, float* __restrict__ eew, int E) {
    int e = blockIdx.x * blockDim.x + threadIdx.x;
    if (e >= E) return;
    int d = dst[e];
    int p = atomicAdd(&cursor[d], 1);
    esrc[p] = src[e];
    eew[p]  = ew[e];
}

// ---------------- Tiled SGEMM (unchanged, known-good) ----------------
__global__ __launch_bounds__(256) void sgemm_kernel(
    const float* __restrict__ A, const float* __restrict__ B, float* __restrict__ C,
    int M, int N, int K) {
    const int BM = 128, BN = 128, BK = 8, TM = 8, TN = 8;
    __shared__ float As[BK][BM];
    __shared__ float Bs[BK][BN];
    const int tid = threadIdx.x;
    const int bM = blockIdx.y * BM;
    const int bN = blockIdx.x * BN;
    const int trow = (tid / 16) * TM;
    const int tcol = (tid % 16) * TN;
    const int aRow = tid >> 1, aCol = (tid & 1) * 4;
    const int bRow = tid >> 5, bCol = (tid & 31) * 4;

    float acc[TM][TN];
    #pragma unroll
    for (int i = 0; i < TM; i++)
        #pragma unroll
        for (int j = 0; j < TN; j++) acc[i][j] = 0.f;

    for (int k0 = 0; k0 < K; k0 += BK) {
        float4 av = make_float4(0.f, 0.f, 0.f, 0.f);
        int arow_g = bM + aRow;
        if (arow_g < M)
            av = *reinterpret_cast<const float4*>(A + (size_t)arow_g * K + k0 + aCol);
        As[aCol + 0][aRow] = av.x;
        As[aCol + 1][aRow] = av.y;
        As[aCol + 2][aRow] = av.z;
        As[aCol + 3][aRow] = av.w;
        float4 bv = make_float4(0.f, 0.f, 0.f, 0.f);
        int bcol_g = bN + bCol;
        if (bcol_g < N)
            bv = *reinterpret_cast<const float4*>(B + (size_t)(k0 + bRow) * N + bcol_g);
        *reinterpret_cast<float4*>(&Bs[bRow][bCol]) = bv;
        __syncthreads();

        #pragma unroll
        for (int kk = 0; kk < BK; kk++) {
            float a[TM], b[TN];
            #pragma unroll
            for (int i = 0; i < TM; i++) a[i] = As[kk][trow + i];
            #pragma unroll
            for (int j = 0; j < TN; j++) b[j] = Bs[kk][tcol + j];
            #pragma unroll
            for (int i = 0; i < TM; i++)
                #pragma unroll
                for (int j = 0; j < TN; j++)
                    acc[i][j] = fmaf(a[i], b[j], acc[i][j]);
        }
        __syncthreads();
    }

    #pragma unroll
    for (int i = 0; i < TM; i++) {
        int row = bM + trow + i;
        if (row >= M) continue;
        #pragma unroll
        for (int j = 0; j < TN; j += 4) {
            int col = bN + tcol + j;
            if (col < N) {
                float4 v = make_float4(acc[i][j], acc[i][j+1], acc[i][j+2], acc[i][j+3]);
                *reinterpret_cast<float4*>(C + (size_t)row * N + col) = v;
            }
        }
    }
}

// ---------------- Per-(node,head) attention dot products ----------------
__global__ void attn_coef_kernel(const float* __restrict__ h,
                                 const float* __restrict__ ws_all,
                                 const float* __restrict__ wd_all,
                                 float* __restrict__ asrc, float* __restrict__ adst,
                                 int H, int C) {
    int n = blockIdx.x, hd = blockIdx.y;
    const float* row = h + ((size_t)n * H + hd) * C;
    const float* ws = ws_all + (size_t)hd * C;
    const float* wd = wd_all + (size_t)hd * C;
    float ss = 0.f, sd = 0.f;
    for (int c = threadIdx.x; c < C; c += blockDim.x) {
        float v = row[c];
        ss += v * ws[c];
        sd += v * wd[c];
    }
    #pragma unroll
    for (int o = 16; o; o >>= 1) {
        ss += __shfl_down_sync(0xffffffffu, ss, o);
        sd += __shfl_down_sync(0xffffffffu, sd, o);
    }
    __shared__ float sss[8], ssd[8];
    int w = threadIdx.x >> 5, l = threadIdx.x & 31;
    if (l == 0) { sss[w] = ss; ssd[w] = sd; }
    __syncthreads();
    if (threadIdx.x == 0) {
        float a = 0.f, b = 0.f;
        int nw = blockDim.x >> 5;
        for (int i = 0; i < nw; i++) { a += sss[i]; b += ssd[i]; }
        asrc[n * H + hd] = a;
        adst[n * H + hd] = b;
    }
}

// ---------------- ce[h] = dot(We[h,:], ae[h,:]) ----------------
__global__ void ce_kernel(const float* __restrict__ We, const float* __restrict__ ae,
                          float* __restrict__ ce, int C) {
    int hd = blockIdx.x;
    float s = 0.f;
    for (int c = threadIdx.x; c < C; c += blockDim.x)
        s += We[(size_t)hd * C + c] * ae[(size_t)hd * C + c];
    #pragma unroll
    for (int o = 16; o; o >>= 1) s += __shfl_down_sync(0xffffffffu, s, o);
    __shared__ float sm[8];
    int w = threadIdx.x >> 5, l = threadIdx.x & 31;
    if (l == 0) sm[w] = s;
    __syncthreads();
    if (threadIdx.x == 0) {
        float a = 0.f;
        int nw = blockDim.x >> 5;
        for (int i = 0; i < nw; i++) a += sm[i];
        ce[hd] = a;
    }
}

// ---------------- CSR segment softmax: one warp per (dst,head) --------------
// Writes unnormalized exp(alpha - max) into g_alpha[k*H+h] and denom[d*H+h].
__global__ void softmax_csr_kernel(const int* __restrict__ rowptr,
                                   const int* __restrict__ esrc,
                                   const float* __restrict__ eew,
                                   const float* __restrict__ asrc,
                                   const float* __restrict__ adst,
                                   const float* __restrict__ ce,
                                   float* __restrict__ alpha,
                                   float* __restrict__ denom,
                                   int H) {
    int gw = blockIdx.x * (blockDim.x >> 5) + (threadIdx.x >> 5);
    int lane = threadIdx.x & 31;
    int d = gw / H, h = gw - d * H;
    if (d >= NN) return;
    int b = rowptr[d], e = rowptr[d + 1];
    float ad  = adst[d * H + h];
    float ceh = ce[h];
    float m = -3.402823466e+38f;
    for (int k = b + lane; k < e; k += 32) {
        float a = asrc[esrc[k] * H + h] + ad + eew[k] * ceh;
        a = a > 0.f ? a : NEG_SLOPE * a;
        alpha[(size_t)k * H + h] = a;
        m = fmaxf(m, a);
    }
    #pragma unroll
    for (int o = 16; o; o >>= 1) m = fmaxf(m, __shfl_xor_sync(0xffffffffu, m, o));
    float s = 0.f;
    for (int k = b + lane; k < e; k += 32) {
        float ex = __expf(alpha[(size_t)k * H + h] - m);
        alpha[(size_t)k * H + h] = ex;
        s += ex;
    }
    #pragma unroll
    for (int o = 16; o; o >>= 1) s += __shfl_xor_sync(0xffffffffu, s, o);
    if (lane == 0) denom[d * H + h] = s;
}

// ---------------- CSR gather aggregation, H=8, C=128 ------------------------
// One block (256 thr = 8 warps) per dst node; warp w handles head w.
// out[d, w*128 + lane*4 .. +3] = relu( sum_e coef_e * h[src_e, w, ...] + bias )
__global__ __launch_bounds__(256) void agg8x128_kernel(
    const int* __restrict__ rowptr, const int* __restrict__ esrc,
    const float* __restrict__ alpha, const float* __restrict__ denom,
    const float* __restrict__ h, const float* __restrict__ bias,
    float* __restrict__ out) {
    int d = blockIdx.x;
    int w = threadIdx.x >> 5, lane = threadIdx.x & 31;
    int b = rowptr[d], e = rowptr[d + 1];
    float inv = 1.f / (denom[d * HEADS + w] + 1e-16f);
    float4 acc = make_float4(0.f, 0.f, 0.f, 0.f);
    int col = w * HID + lane * 4;
    #pragma unroll 2
    for (int k = b; k < e; k++) {
        int s = esrc[k];
        float coef = alpha[(size_t)k * HEADS + w] * inv;
        float4 v = *reinterpret_cast<const float4*>(h + (size_t)s * HC + col);
        acc.x = fmaf(v.x, coef, acc.x);
        acc.y = fmaf(v.y, coef, acc.y);
        acc.z = fmaf(v.z, coef, acc.z);
        acc.w = fmaf(v.w, coef, acc.w);
    }
    float4 bv = *reinterpret_cast<const float4*>(bias + col);
    acc.x = fmaxf(acc.x + bv.x, 0.f);
    acc.y = fmaxf(acc.y + bv.y, 0.f);
    acc.z = fmaxf(acc.z + bv.z, 0.f);
    acc.w = fmaxf(acc.w + bv.w, 0.f);
    *reinterpret_cast<float4*>(out + (size_t)d * HC + col) = acc;
}

// ---------------- CSR gather aggregation, H=1, C=768 (layer 3) --------------
// One block (256 thr) per dst node, 3 cols per thread, no relu.
__global__ __launch_bounds__(256) void agg768_kernel(
    const int* __restrict__ rowptr, const int* __restrict__ esrc,
    const float* __restrict__ alpha, const float* __restrict__ denom,
    const float* __restrict__ h, const float* __restrict__ bias,
    float* __restrict__ out) {
    int d = blockIdx.x;
    int tid = threadIdx.x;
    int b = rowptr[d], e = rowptr[d + 1];
    float inv = 1.f / (denom[d] + 1e-16f);
    float a0 = 0.f, a1 = 0.f, a2 = 0.f;
    #pragma unroll 2
    for (int k = b; k < e; k++) {
        int s = esrc[k];
        float coef = alpha[k] * inv;
        const float* hp = h + (size_t)s * OUTC;
        a0 = fmaf(hp[tid],       coef, a0);
        a1 = fmaf(hp[tid + 256], coef, a1);
        a2 = fmaf(hp[tid + 512], coef, a2);
    }
    float* op = out + (size_t)d * OUTC;
    op[tid]       = a0 + bias[tid];
    op[tid + 256] = a1 + bias[tid + 256];
    op[tid + 512] = a2 + bias[tid + 512];
}

// ---------------- host-side layer driver ----------------
static void run_layer_common(const float* in, int F_in, const float* W,
                             const float* a_s, const float* a_d,
                             const float* We, const float* ae,
                             int H, int C, float* hbuf,
                             float* asrc, float* adst, float* alpha,
                             float* denom, float* ce,
                             const int* rowptr, const int* esrc, const float* eew) {
    int F_out = H * C;
    dim3 ggrid((F_out + 127) / 128, (NN + 127) / 128);
    sgemm_kernel<<<ggrid, 256>>>(in, W, hbuf, NN, F_out, F_in);
    attn_coef_kernel<<<dim3(NN, H), 128>>>(hbuf, a_s, a_d, asrc, adst, H, C);
    ce_kernel<<<H, 128>>>(We, ae, ce, C);
    int nwarp = NN * H;
    softmax_csr_kernel<<<(nwarp + 7) / 8, 256>>>(rowptr, esrc, eew, asrc, adst, ce,
                                                 alpha, denom, H);
}

extern "C" void kernel_launch(void* const* d_in, const int* in_sizes, int n_in,
                              void* d_out, int out_size) {
    const float* x   = (const float*)d_in[0];
    const int*   ei  = (const int*)d_in[1];
    const float* ew  = (const float*)d_in[2];
    const float* W1  = (const float*)d_in[3];
    const float* as1 = (const float*)d_in[4];
    const float* ad1 = (const float*)d_in[5];
    const float* We1 = (const float*)d_in[6];
    const float* ae1 = (const float*)d_in[7];
    const float* b1  = (const float*)d_in[8];
    const float* W2  = (const float*)d_in[9];
    const float* as2 = (const float*)d_in[10];
    const float* ad2 = (const float*)d_in[11];
    const float* We2 = (const float*)d_in[12];
    const float* ae2 = (const float*)d_in[13];
    const float* b2  = (const float*)d_in[14];
    const float* W3  = (const float*)d_in[15];
    const float* as3 = (const float*)d_in[16];
    const float* ad3 = (const float*)d_in[17];
    const float* We3 = (const float*)d_in[18];
    const float* ae3 = (const float*)d_in[19];
    const float* b3  = (const float*)d_in[20];

    const int E = in_sizes[2];
    const int* src = ei;
    const int* dst = ei + E;

    float *bufA, *bufB, *xT, *asrc, *adst, *alpha, *denom, *ce, *eew;
    int *deg, *rowptr, *cursor, *esrc;
    cudaGetSymbolAddress((void**)&bufA,   g_bufA);
    cudaGetSymbolAddress((void**)&bufB,   g_bufB);
    cudaGetSymbolAddress((void**)&xT,     g_xT);
    cudaGetSymbolAddress((void**)&asrc,   g_asrc);
    cudaGetSymbolAddress((void**)&adst,   g_adst);
    cudaGetSymbolAddress((void**)&alpha,  g_alpha);
    cudaGetSymbolAddress((void**)&denom,  g_denom);
    cudaGetSymbolAddress((void**)&ce,     g_ce);
    cudaGetSymbolAddress((void**)&deg,    g_deg);
    cudaGetSymbolAddress((void**)&rowptr, g_rowptr);
    cudaGetSymbolAddress((void**)&cursor, g_cursor);
    cudaGetSymbolAddress((void**)&esrc,   g_esrc);
    cudaGetSymbolAddress((void**)&eew,    g_eew);

    float* out = (float*)d_out;

    // ---- CSR build ----
    zero_deg_kernel<<<(NN + 255) / 256, 256>>>(deg, NN);
    hist_kernel<<<(E + 255) / 256, 256>>>(dst, deg, E);
    scan_kernel<<<1, 1024>>>(deg, rowptr, NN);
    copy_cursor_kernel<<<(NN + 255) / 256, 256>>>(rowptr, cursor, NN);
    build_csr_kernel<<<(E + 255) / 256, 256>>>(src, dst, ew, cursor, esrc, eew, E);

    // ---- Transpose x: [1, SEQ, N] -> [N, SEQ] ----
    int ts = NN * SEQ;
    transpose_x_kernel<<<(ts + 255) / 256, 256>>>(x, xT, NN, SEQ);

    // ---- Layer 1: h -> bufA, out -> bufB (relu) ----
    run_layer_common(xT, SEQ, W1, as1, ad1, We1, ae1, HEADS, HID,
                     bufA, asrc, adst, alpha, denom, ce, rowptr, esrc, eew);
    agg8x128_kernel<<<NN, 256>>>(rowptr, esrc, alpha, denom, bufA, b1, bufB);

    // ---- Layer 2: h -> bufA, out -> bufB ----
    run_layer_common(bufB, HC, W2, as2, ad2, We2, ae2, HEADS, HID,
                     bufA, asrc, adst, alpha, denom, ce, rowptr, esrc, eew);
    agg8x128_kernel<<<NN, 256>>>(rowptr, esrc, alpha, denom, bufA, b2, bufB);

    // ---- Layer 3: h -> bufA, out -> d_out (no relu) ----
    run_layer_common(bufB, HC, W3, as3, ad3, We3, ae3, 1, OUTC,
                     bufA, asrc, adst, alpha, denom, ce, rowptr, esrc, eew);
    agg768_kernel<<<NN, 256>>>(rowptr, esrc, alpha, denom, bufA, b3, out);
}

// round 5
// speedup vs baseline: 1.9847x; 1.1680x over previous
#include <cuda_runtime.h>
#include <cuda_bf16.h>
#include <cstdint>

// ---------------- Problem constants ----------------
#define NN    10000
#define SEQ   96
#define HID   128
#define HEADS 8
#define HC    (HID*HEADS)   // 1024
#define OUTC  768
#define EMAX  160000
#define NEG_SLOPE 0.2f

// ---------------- Scratch (device globals) ----------------
__device__ float g_bufA[NN * HC];
__device__ float g_bufB[NN * HC];
__device__ float g_xT[NN * SEQ];
__device__ float g_asrc[NN * HEADS];
__device__ float g_adst[NN * HEADS];
__device__ float g_alpha[EMAX * HEADS];
__device__ float g_denom[NN * HEADS];
__device__ float g_ce[HEADS];
// CSR
__device__ int   g_deg[NN];
__device__ int   g_rowptr[NN + 1];
__device__ int   g_cursor[NN];
__device__ int   g_esrc[EMAX];
__device__ float g_eew[EMAX];

// ---------------- Transpose x: [S,N] -> [N,S] ----------------
__global__ void transpose_x_kernel(const float* __restrict__ x, float* __restrict__ xT,
                                   int n, int s) {
    int i = blockIdx.x * blockDim.x + threadIdx.x;
    if (i >= n * s) return;
    int sr = i / n, nc = i % n;
    xT[(size_t)nc * s + sr] = x[i];
}

// ---------------- CSR build ----------------
__global__ void zero_deg_kernel(int* __restrict__ deg, int n) {
    int i = blockIdx.x * blockDim.x + threadIdx.x;
    if (i < n) deg[i] = 0;
}
__global__ void hist_kernel(const int* __restrict__ dst, int* __restrict__ deg, int E) {
    int e = blockIdx.x * blockDim.x + threadIdx.x;
    if (e < E) atomicAdd(&deg[dst[e]], 1);
}
__global__ __launch_bounds__(1024) void scan_kernel(const int* __restrict__ deg,
                                                    int* __restrict__ rowptr, int n) {
    __shared__ int warp_sums[32];
    const int T = 1024;
    int tid = threadIdx.x;
    int chunk = (n + T - 1) / T;
    int start = tid * chunk;
    int local = 0;
    for (int i = 0; i < chunk; i++) {
        int idx = start + i;
        if (idx < n) local += deg[idx];
    }
    int lane = tid & 31, w = tid >> 5;
    int v = local;
    #pragma unroll
    for (int o = 1; o < 32; o <<= 1) {
        int t = __shfl_up_sync(0xffffffffu, v, o);
        if (lane >= o) v += t;
    }
    if (lane == 31) warp_sums[w] = v;
    __syncthreads();
    if (w == 0) {
        int s = warp_sums[lane];
        #pragma unroll
        for (int o = 1; o < 32; o <<= 1) {
            int t = __shfl_up_sync(0xffffffffu, s, o);
            if (lane >= o) s += t;
        }
        warp_sums[lane] = s;
    }
    __syncthreads();
    int excl = v - local + (w > 0 ? warp_sums[w - 1] : 0);
    int run = excl;
    for (int i = 0; i < chunk; i++) {
        int idx = start + i;
        if (idx < n) { rowptr[idx] = run; run += deg[idx]; }
    }
    if (start < n && start + chunk >= n) rowptr[n] = run;
}
__global__ void copy_cursor_kernel(const int* __restrict__ rowptr, int* __restrict__ cursor, int n) {
    int i = blockIdx.x * blockDim.x + threadIdx.x;
    if (i < n) cursor[i] = rowptr[i];
}
__global__ void build_csr_kernel(const int* __restrict__ src, const int* __restrict__ dst,
                                 const float* __restrict__ ew,
                                 int* __restrict__ cursor,
                                 int* __restrict__ esrc, float* __restrict__ eew, int E) {
    int e = blockIdx.x * blockDim.x + threadIdx.x;
    if (e >= E) return;
    int d = dst[e];
    int p = atomicAdd(&cursor[d], 1);
    esrc[p] = src[e];
    eew[p]  = ew[e];
}

// ---------------- 3xTF32 tensor-core GEMM ----------------
// C[M,N] = A[M,K] * B[K,N], row-major. Requires K%16==0, N%128==0.
// Block 128x128x16, 256 threads = 8 warps (2 in M x 4 in N), warp tile 64x32.
__device__ __forceinline__ uint32_t f2tf(float f) {
    uint32_t r; asm("cvt.rna.tf32.f32 %0, %1;" : "=r"(r) : "f"(f)); return r;
}
__device__ __forceinline__ void mma_tf32(float c[4], uint32_t a0, uint32_t a1,
                                         uint32_t a2, uint32_t a3,
                                         uint32_t b0, uint32_t b1) {
    asm volatile(
        "mma.sync.aligned.m16n8k8.row.col.f32.tf32.tf32.f32 "
        "{%0,%1,%2,%3}, {%4,%5,%6,%7}, {%8,%9}, {%0,%1,%2,%3};"
        : "+f"(c[0]), "+f"(c[1]), "+f"(c[2]), "+f"(c[3])
        : "r"(a0), "r"(a1), "r"(a2), "r"(a3), "r"(b0), "r"(b1));
}

__global__ __launch_bounds__(256) void tf32_gemm_kernel(
    const float* __restrict__ A, const float* __restrict__ B, float* __restrict__ C,
    int M, int N, int K) {
    __shared__ uint32_t sAhi[16][132];
    __shared__ uint32_t sAlo[16][132];
    __shared__ uint32_t sBhi[16][132];
    __shared__ uint32_t sBlo[16][132];

    const int tid = threadIdx.x;
    const int bM = blockIdx.y * 128;
    const int bN = blockIdx.x * 128;
    const int lane = tid & 31, wid = tid >> 5;
    const int gr = lane >> 2, ctg = lane & 3;
    const int wm = (wid & 1) * 64;       // warp row base
    const int wn = (wid >> 1) * 32;      // warp col base

    float c[4][4][4];
    #pragma unroll
    for (int i = 0; i < 4; i++)
        #pragma unroll
        for (int j = 0; j < 4; j++)
            #pragma unroll
            for (int q = 0; q < 4; q++) c[i][j][q] = 0.f;

    // A: thread loads rows {tid/4, tid/4+64}, cols 4*(tid&3)..+3 of the 128x16 tile
    const int ar = tid >> 2;
    const int ac = (tid & 3) * 4;
    // B: thread loads row tid/16, float4 cols (tid&15) and (tid&15)+16 of 16x128 tile
    const int br = tid >> 4;
    const int bc = (tid & 15) * 4;

    const int nk = K / 16;
    float4 aReg[2], bReg[2];

    // prefetch tile 0
    {
        #pragma unroll
        for (int i = 0; i < 2; i++) {
            int row = bM + ar + 64 * i;
            aReg[i] = (row < M) ? *reinterpret_cast<const float4*>(A + (size_t)row * K + ac)
                                : make_float4(0.f, 0.f, 0.f, 0.f);
            bReg[i] = *reinterpret_cast<const float4*>(B + (size_t)br * N + bN + bc + 64 * i);
        }
    }

    for (int kt = 0; kt < nk; kt++) {
        // convert+store current tile to smem
        #pragma unroll
        for (int i = 0; i < 2; i++) {
            float va[4] = {aReg[i].x, aReg[i].y, aReg[i].z, aReg[i].w};
            #pragma unroll
            for (int j = 0; j < 4; j++) {
                uint32_t hi = f2tf(va[j]);
                uint32_t lo = f2tf(va[j] - __uint_as_float(hi));
                sAhi[ac + j][ar + 64 * i] = hi;
                sAlo[ac + j][ar + 64 * i] = lo;
            }
            float vb[4] = {bReg[i].x, bReg[i].y, bReg[i].z, bReg[i].w};
            uint32_t bh[4], bl[4];
            #pragma unroll
            for (int j = 0; j < 4; j++) {
                bh[j] = f2tf(vb[j]);
                bl[j] = f2tf(vb[j] - __uint_as_float(bh[j]));
            }
            *reinterpret_cast<uint4*>(&sBhi[br][bc + 64 * i]) = make_uint4(bh[0], bh[1], bh[2], bh[3]);
            *reinterpret_cast<uint4*>(&sBlo[br][bc + 64 * i]) = make_uint4(bl[0], bl[1], bl[2], bl[3]);
        }
        __syncthreads();

        // prefetch next tile
        if (kt + 1 < nk) {
            int k0 = (kt + 1) * 16;
            #pragma unroll
            for (int i = 0; i < 2; i++) {
                int row = bM + ar + 64 * i;
                aReg[i] = (row < M) ? *reinterpret_cast<const float4*>(A + (size_t)row * K + k0 + ac)
                                    : make_float4(0.f, 0.f, 0.f, 0.f);
                bReg[i] = *reinterpret_cast<const float4*>(B + (size_t)(k0 + br) * N + bN + bc + 64 * i);
            }
        }

        // compute: two k8 sub-steps
        #pragma unroll
        for (int h8 = 0; h8 < 2; h8++) {
            const int kk = h8 * 8;
            uint32_t ahi[4][4], alo[4][4], bhi[4][2], blo[4][2];
            #pragma unroll
            for (int mt = 0; mt < 4; mt++) {
                int rb = wm + mt * 16 + gr;
                ahi[mt][0] = sAhi[kk + ctg][rb];
                ahi[mt][1] = sAhi[kk + ctg][rb + 8];
                ahi[mt][2] = sAhi[kk + ctg + 4][rb];
                ahi[mt][3] = sAhi[kk + ctg + 4][rb + 8];
                alo[mt][0] = sAlo[kk + ctg][rb];
                alo[mt][1] = sAlo[kk + ctg][rb + 8];
                alo[mt][2] = sAlo[kk + ctg + 4][rb];
                alo[mt][3] = sAlo[kk + ctg + 4][rb + 8];
            }
            #pragma unroll
            for (int nt = 0; nt < 4; nt++) {
                int cb = wn + nt * 8 + gr;
                bhi[nt][0] = sBhi[kk + ctg][cb];
                bhi[nt][1] = sBhi[kk + ctg + 4][cb];
                blo[nt][0] = sBlo[kk + ctg][cb];
                blo[nt][1] = sBlo[kk + ctg + 4][cb];
            }
            #pragma unroll
            for (int mt = 0; mt < 4; mt++)
                #pragma unroll
                for (int nt = 0; nt < 4; nt++) {
                    mma_tf32(c[mt][nt], ahi[mt][0], ahi[mt][1], ahi[mt][2], ahi[mt][3],
                             bhi[nt][0], bhi[nt][1]);
                    mma_tf32(c[mt][nt], ahi[mt][0], ahi[mt][1], ahi[mt][2], ahi[mt][3],
                             blo[nt][0], blo[nt][1]);
                    mma_tf32(c[mt][nt], alo[mt][0], alo[mt][1], alo[mt][2], alo[mt][3],
                             bhi[nt][0], bhi[nt][1]);
                }
        }
        __syncthreads();
    }

    // epilogue
    #pragma unroll
    for (int mt = 0; mt < 4; mt++) {
        int r0 = bM + wm + mt * 16 + gr;
        int r1 = r0 + 8;
        #pragma unroll
        for (int nt = 0; nt < 4; nt++) {
            int col = bN + wn + nt * 8 + 2 * ctg;
            if (r0 < M)
                *reinterpret_cast<float2*>(C + (size_t)r0 * N + col) =
                    make_float2(c[mt][nt][0], c[mt][nt][1]);
            if (r1 < M)
                *reinterpret_cast<float2*>(C + (size_t)r1 * N + col) =
                    make_float2(c[mt][nt][2], c[mt][nt][3]);
        }
    }
}

// ---------------- Per-(node,head) attention dot products ----------------
__global__ void attn_coef_kernel(const float* __restrict__ h,
                                 const float* __restrict__ ws_all,
                                 const float* __restrict__ wd_all,
                                 float* __restrict__ asrc, float* __restrict__ adst,
                                 int H, int C) {
    int n = blockIdx.x, hd = blockIdx.y;
    const float* row = h + ((size_t)n * H + hd) * C;
    const float* ws = ws_all + (size_t)hd * C;
    const float* wd = wd_all + (size_t)hd * C;
    float ss = 0.f, sd = 0.f;
    for (int c = threadIdx.x; c < C; c += blockDim.x) {
        float v = row[c];
        ss += v * ws[c];
        sd += v * wd[c];
    }
    #pragma unroll
    for (int o = 16; o; o >>= 1) {
        ss += __shfl_down_sync(0xffffffffu, ss, o);
        sd += __shfl_down_sync(0xffffffffu, sd, o);
    }
    __shared__ float sss[8], ssd[8];
    int w = threadIdx.x >> 5, l = threadIdx.x & 31;
    if (l == 0) { sss[w] = ss; ssd[w] = sd; }
    __syncthreads();
    if (threadIdx.x == 0) {
        float a = 0.f, b = 0.f;
        int nw = blockDim.x >> 5;
        for (int i = 0; i < nw; i++) { a += sss[i]; b += ssd[i]; }
        asrc[n * H + hd] = a;
        adst[n * H + hd] = b;
    }
}

// ---------------- ce[h] = dot(We[h,:], ae[h,:]) ----------------
__global__ void ce_kernel(const float* __restrict__ We, const float* __restrict__ ae,
                          float* __restrict__ ce, int C) {
    int hd = blockIdx.x;
    float s = 0.f;
    for (int c = threadIdx.x; c < C; c += blockDim.x)
        s += We[(size_t)hd * C + c] * ae[(size_t)hd * C + c];
    #pragma unroll
    for (int o = 16; o; o >>= 1) s += __shfl_down_sync(0xffffffffu, s, o);
    __shared__ float sm[8];
    int w = threadIdx.x >> 5, l = threadIdx.x & 31;
    if (l == 0) sm[w] = s;
    __syncthreads();
    if (threadIdx.x == 0) {
        float a = 0.f;
        int nw = blockDim.x >> 5;
        for (int i = 0; i < nw; i++) a += sm[i];
        ce[hd] = a;
    }
}

// ---------------- CSR segment softmax: one warp per (dst,head) --------------
__global__ void softmax_csr_kernel(const int* __restrict__ rowptr,
                                   const int* __restrict__ esrc,
                                   const float* __restrict__ eew,
                                   const float* __restrict__ asrc,
                                   const float* __restrict__ adst,
                                   const float* __restrict__ ce,
                                   float* __restrict__ alpha,
                                   float* __restrict__ denom,
                                   int H) {
    int gw = blockIdx.x * (blockDim.x >> 5) + (threadIdx.x >> 5);
    int lane = threadIdx.x & 31;
    int d = gw / H, h = gw - d * H;
    if (d >= NN) return;
    int b = rowptr[d], e = rowptr[d + 1];
    float ad  = adst[d * H + h];
    float ceh = ce[h];
    float m = -3.402823466e+38f;
    for (int k = b + lane; k < e; k += 32) {
        float a = asrc[esrc[k] * H + h] + ad + eew[k] * ceh;
        a = a > 0.f ? a : NEG_SLOPE * a;
        alpha[(size_t)k * H + h] = a;
        m = fmaxf(m, a);
    }
    #pragma unroll
    for (int o = 16; o; o >>= 1) m = fmaxf(m, __shfl_xor_sync(0xffffffffu, m, o));
    float s = 0.f;
    for (int k = b + lane; k < e; k += 32) {
        float ex = __expf(alpha[(size_t)k * H + h] - m);
        alpha[(size_t)k * H + h] = ex;
        s += ex;
    }
    #pragma unroll
    for (int o = 16; o; o >>= 1) s += __shfl_xor_sync(0xffffffffu, s, o);
    if (lane == 0) denom[d * H + h] = s;
}

// ---------------- CSR gather aggregation, H=8, C=128 ------------------------
__global__ __launch_bounds__(256) void agg8x128_kernel(
    const int* __restrict__ rowptr, const int* __restrict__ esrc,
    const float* __restrict__ alpha, const float* __restrict__ denom,
    const float* __restrict__ h, const float* __restrict__ bias,
    float* __restrict__ out) {
    int d = blockIdx.x;
    int w = threadIdx.x >> 5, lane = threadIdx.x & 31;
    int b = rowptr[d], e = rowptr[d + 1];
    float inv = 1.f / (denom[d * HEADS + w] + 1e-16f);
    float4 acc = make_float4(0.f, 0.f, 0.f, 0.f);
    int col = w * HID + lane * 4;
    #pragma unroll 4
    for (int k = b; k < e; k++) {
        int s = esrc[k];
        float coef = alpha[(size_t)k * HEADS + w] * inv;
        float4 v = *reinterpret_cast<const float4*>(h + (size_t)s * HC + col);
        acc.x = fmaf(v.x, coef, acc.x);
        acc.y = fmaf(v.y, coef, acc.y);
        acc.z = fmaf(v.z, coef, acc.z);
        acc.w = fmaf(v.w, coef, acc.w);
    }
    float4 bv = *reinterpret_cast<const float4*>(bias + col);
    acc.x = fmaxf(acc.x + bv.x, 0.f);
    acc.y = fmaxf(acc.y + bv.y, 0.f);
    acc.z = fmaxf(acc.z + bv.z, 0.f);
    acc.w = fmaxf(acc.w + bv.w, 0.f);
    *reinterpret_cast<float4*>(out + (size_t)d * HC + col) = acc;
}

// ---------------- CSR gather aggregation, H=1, C=768 (layer 3) --------------
__global__ __launch_bounds__(256) void agg768_kernel(
    const int* __restrict__ rowptr, const int* __restrict__ esrc,
    const float* __restrict__ alpha, const float* __restrict__ denom,
    const float* __restrict__ h, const float* __restrict__ bias,
    float* __restrict__ out) {
    int d = blockIdx.x;
    int tid = threadIdx.x;
    int b = rowptr[d], e = rowptr[d + 1];
    float inv = 1.f / (denom[d] + 1e-16f);
    float a0 = 0.f, a1 = 0.f, a2 = 0.f;
    #pragma unroll 4
    for (int k = b; k < e; k++) {
        int s = esrc[k];
        float coef = alpha[k] * inv;
        const float* hp = h + (size_t)s * OUTC;
        a0 = fmaf(hp[tid],       coef, a0);
        a1 = fmaf(hp[tid + 256], coef, a1);
        a2 = fmaf(hp[tid + 512], coef, a2);
    }
    float* op = out + (size_t)d * OUTC;
    op[tid]       = a0 + bias[tid];
    op[tid + 256] = a1 + bias[tid + 256];
    op[tid + 512] = a2 + bias[tid + 512];
}

// ---------------- host-side layer driver ----------------
static void run_layer_common(const float* in, int F_in, const float* W,
                             const float* a_s, const float* a_d,
                             const float* We, const float* ae,
                             int H, int C, float* hbuf,
                             float* asrc, float* adst, float* alpha,
                             float* denom, float* ce,
                             const int* rowptr, const int* esrc, const float* eew) {
    int F_out = H * C;
    dim3 ggrid(F_out / 128, (NN + 127) / 128);
    tf32_gemm_kernel<<<ggrid, 256>>>(in, W, hbuf, NN, F_out, F_in);
    attn_coef_kernel<<<dim3(NN, H), 128>>>(hbuf, a_s, a_d, asrc, adst, H, C);
    ce_kernel<<<H, 128>>>(We, ae, ce, C);
    int nwarp = NN * H;
    softmax_csr_kernel<<<(nwarp + 7) / 8, 256>>>(rowptr, esrc, eew, asrc, adst, ce,
                                                 alpha, denom, H);
}

extern "C" void kernel_launch(void* const* d_in, const int* in_sizes, int n_in,
                              void* d_out, int out_size) {
    const float* x   = (const float*)d_in[0];
    const int*   ei  = (const int*)d_in[1];
    const float* ew  = (const float*)d_in[2];
    const float* W1  = (const float*)d_in[3];
    const float* as1 = (const float*)d_in[4];
    const float* ad1 = (const float*)d_in[5];
    const float* We1 = (const float*)d_in[6];
    const float* ae1 = (const float*)d_in[7];
    const float* b1  = (const float*)d_in[8];
    const float* W2  = (const float*)d_in[9];
    const float* as2 = (const float*)d_in[10];
    const float* ad2 = (const float*)d_in[11];
    const float* We2 = (const float*)d_in[12];
    const float* ae2 = (const float*)d_in[13];
    const float* b2  = (const float*)d_in[14];
    const float* W3  = (const float*)d_in[15];
    const float* as3 = (const float*)d_in[16];
    const float* ad3 = (const float*)d_in[17];
    const float* We3 = (const float*)d_in[18];
    const float* ae3 = (const float*)d_in[19];
    const float* b3  = (const float*)d_in[20];

    const int E = in_sizes[2];
    const int* src = ei;
    const int* dst = ei + E;

    float *bufA, *bufB, *xT, *asrc, *adst, *alpha, *denom, *ce, *eew;
    int *deg, *rowptr, *cursor, *esrc;
    cudaGetSymbolAddress((void**)&bufA,   g_bufA);
    cudaGetSymbolAddress((void**)&bufB,   g_bufB);
    cudaGetSymbolAddress((void**)&xT,     g_xT);
    cudaGetSymbolAddress((void**)&asrc,   g_asrc);
    cudaGetSymbolAddress((void**)&adst,   g_adst);
    cudaGetSymbolAddress((void**)&alpha,  g_alpha);
    cudaGetSymbolAddress((void**)&denom,  g_denom);
    cudaGetSymbolAddress((void**)&ce,     g_ce);
    cudaGetSymbolAddress((void**)&deg,    g_deg);
    cudaGetSymbolAddress((void**)&rowptr, g_rowptr);
    cudaGetSymbolAddress((void**)&cursor, g_cursor);
    cudaGetSymbolAddress((void**)&esrc,   g_esrc);
    cudaGetSymbolAddress((void**)&eew,    g_eew);

    float* out = (float*)d_out;

    // ---- CSR build ----
    zero_deg_kernel<<<(NN + 255) / 256, 256>>>(deg, NN);
    hist_kernel<<<(E + 255) / 256, 256>>>(dst, deg, E);
    scan_kernel<<<1, 1024>>>(deg, rowptr, NN);
    copy_cursor_kernel<<<(NN + 255) / 256, 256>>>(rowptr, cursor, NN);
    build_csr_kernel<<<(E + 255) / 256, 256>>>(src, dst, ew, cursor, esrc, eew, E);

    // ---- Transpose x ----
    int ts = NN * SEQ;
    transpose_x_kernel<<<(ts + 255) / 256, 256>>>(x, xT, NN, SEQ);

    // ---- Layer 1 ----
    run_layer_common(xT, SEQ, W1, as1, ad1, We1, ae1, HEADS, HID,
                     bufA, asrc, adst, alpha, denom, ce, rowptr, esrc, eew);
    agg8x128_kernel<<<NN, 256>>>(rowptr, esrc, alpha, denom, bufA, b1, bufB);

    // ---- Layer 2 ----
    run_layer_common(bufB, HC, W2, as2, ad2, We2, ae2, HEADS, HID,
                     bufA, asrc, adst, alpha, denom, ce, rowptr, esrc, eew);
    agg8x128_kernel<<<NN, 256>>>(rowptr, esrc, alpha, denom, bufA, b2, bufB);

    // ---- Layer 3 ----
    run_layer_common(bufB, HC, W3, as3, ad3, We3, ae3, 1, OUTC,
                     bufA, asrc, adst, alpha, denom, ce, rowptr, esrc, eew);
    agg768_kernel<<<NN, 256>>>(rowptr, esrc, alpha, denom, bufA, b3, out);
}